// round 4
// baseline (speedup 1.0000x reference)
#include <cuda_runtime.h>

// Shapes (fixed per reference):
//   x:              [B=64, C=512, H=32, W=32]  fp32   (HW = 1024 contiguous)
//   router_weights: [1, C=512, A=16]
//   router_bias:    [1, 16]
//   bn_gamma/beta:  [1, 512]
//   ln_gamma/beta:  [1, 512]
// Output (concatenated, fp32):
//   new_x   [1,64,512]  -> out[0      .. 32768)
//   logits  [1,64,16]   -> out[32768  .. 33792)
//   probs   [1,64,16]   -> out[33792  .. 34816)

#define B_DIM 64
#define C_DIM 512
#define A_DIM 16
#define HW    1024
#define EPSF  1e-5f

// Scratch (allocation-free rule: __device__ globals)
__device__ float g_sum[B_DIM * C_DIM];
__device__ float g_sq [B_DIM * C_DIM];

// ---------------------------------------------------------------------------
// Kernel A: per-(b,c) spatial sum + sumsq.  One warp per 1024-float tile.
// 8 warps/block, 4096 blocks. Fully coalesced float4 loads, MLP=8 per lane.
// ---------------------------------------------------------------------------
__global__ __launch_bounds__(256) void k_spatial_reduce(const float* __restrict__ x)
{
    int warp = (blockIdx.x * blockDim.x + threadIdx.x) >> 5;   // 0 .. 32767
    int lane = threadIdx.x & 31;

    const float4* p = reinterpret_cast<const float4*>(x) + (size_t)warp * 256;

    float s = 0.f, q = 0.f;
#pragma unroll
    for (int k = 0; k < 8; ++k) {
        float4 v = p[k * 32 + lane];
        s += v.x + v.y + v.z + v.w;
        q += v.x * v.x + v.y * v.y + v.z * v.z + v.w * v.w;
    }
#pragma unroll
    for (int o = 16; o; o >>= 1) {
        s += __shfl_xor_sync(0xFFFFFFFFu, s, o);
        q += __shfl_xor_sync(0xFFFFFFFFu, q, o);
    }
    if (lane == 0) {
        g_sum[warp] = s;
        g_sq [warp] = q;
    }
}

// ---------------------------------------------------------------------------
// Kernel B: per-channel batch stats + new_x.  One warp per channel.
// 8 warps/block, 64 blocks.
// ---------------------------------------------------------------------------
__global__ __launch_bounds__(256) void k_channel_stats(
    const float* __restrict__ bn_gamma,
    const float* __restrict__ bn_beta,
    float* __restrict__ out_newx)          // [64,512]
{
    int c    = blockIdx.x * 8 + (threadIdx.x >> 5);   // 0 .. 511
    int lane = threadIdx.x & 31;

    // lane handles b = lane and b = lane+32
    float s0 = g_sum[lane * C_DIM + c];
    float s1 = g_sum[(lane + 32) * C_DIM + c];
    float q0 = g_sq [lane * C_DIM + c];
    float q1 = g_sq [(lane + 32) * C_DIM + c];

    float S = s0 + s1, Q = q0 + q1;
#pragma unroll
    for (int o = 16; o; o >>= 1) {
        S += __shfl_xor_sync(0xFFFFFFFFu, S, o);
        Q += __shfl_xor_sync(0xFFFFFFFFu, Q, o);
    }
    const float invM = 1.0f / (float)(B_DIM * HW);    // 1/65536
    float mu   = S * invM;
    float var  = Q * invM - mu * mu;
    float rstd = rsqrtf(var + EPSF);

    float g = bn_gamma[c], b = bn_beta[c];
    const float invHW = 1.0f / (float)HW;
    out_newx[lane        * C_DIM + c] = g * (s0 * invHW - mu) * rstd + b;
    out_newx[(lane + 32) * C_DIM + c] = g * (s1 * invHW - mu) * rstd + b;
}

// ---------------------------------------------------------------------------
// Kernel C: weight LayerNorm + routing matmul + softmax.
// 64 blocks (one per batch element b), 512 threads.
// Each block recomputes wn into smem (w is 32KB, L2-resident after block 0).
// ---------------------------------------------------------------------------
__global__ __launch_bounds__(512) void k_route(
    const float* __restrict__ w,          // [512,16]
    const float* __restrict__ rbias,      // [16]
    const float* __restrict__ ln_gamma,   // [512]
    const float* __restrict__ ln_beta,    // [512]
    float* __restrict__ out)              // full output buffer
{
    __shared__ float wn[C_DIM * A_DIM];   // 32 KB, wn[c*16 + a]
    __shared__ float part[512];
    __shared__ float lsh[A_DIM];

    int tid  = threadIdx.x;
    int wa   = tid >> 5;                  // warp id == adapter a (16 warps)
    int lane = tid & 31;
    int b    = blockIdx.x;

    // --- LayerNorm over C of column wa of w ---
    float vals[16];
    float s = 0.f, q = 0.f;
#pragma unroll
    for (int k = 0; k < 16; ++k) {
        float v = w[(lane + k * 32) * A_DIM + wa];
        vals[k] = v;
        s += v; q += v * v;
    }
#pragma unroll
    for (int o = 16; o; o >>= 1) {
        s += __shfl_xor_sync(0xFFFFFFFFu, s, o);
        q += __shfl_xor_sync(0xFFFFFFFFu, q, o);
    }
    float m    = s * (1.0f / (float)C_DIM);
    float var  = q * (1.0f / (float)C_DIM) - m * m;
    float rstd = rsqrtf(var + EPSF);
#pragma unroll
    for (int k = 0; k < 16; ++k) {
        int c = lane + k * 32;
        wn[c * A_DIM + wa] = (vals[k] - m) * rstd * ln_gamma[c] + ln_beta[c];
    }
    __syncthreads();

    // --- logits[b][a]: split the 512-length dot into 32 chunks of 16 ---
    const float* newx = out;                  // [64,512]
    float* logits_out = out + B_DIM * C_DIM;  // [64,16]
    float* probs_out  = logits_out + B_DIM * A_DIM;

    {
        int a     = tid & 15;
        int chunk = tid >> 4;                 // 0..31
        const float* xr = newx + b * C_DIM + chunk * 16;
        const float* wr = wn + (chunk * 16) * A_DIM + a;
        float acc = 0.f;
#pragma unroll
        for (int j = 0; j < 16; ++j)
            acc += xr[j] * wr[j * A_DIM];
        part[tid] = acc;
    }
    __syncthreads();

    if (tid < A_DIM) {
        float acc = rbias[tid];
#pragma unroll
        for (int ch = 0; ch < 32; ++ch)
            acc += part[ch * 16 + tid];
        lsh[tid] = acc;
        logits_out[b * A_DIM + tid] = acc;
    }
    __syncthreads();

    if (tid == 0) {
        float mx = lsh[0];
#pragma unroll
        for (int a = 1; a < A_DIM; ++a) mx = fmaxf(mx, lsh[a]);
        float e[A_DIM]; float ssum = 0.f;
#pragma unroll
        for (int a = 0; a < A_DIM; ++a) { e[a] = __expf(lsh[a] - mx); ssum += e[a]; }
        float inv = 1.0f / ssum;
#pragma unroll
        for (int a = 0; a < A_DIM; ++a) probs_out[b * A_DIM + a] = e[a] * inv;
    }
}

// ---------------------------------------------------------------------------
extern "C" void kernel_launch(void* const* d_in, const int* in_sizes, int n_in,
                              void* d_out, int out_size)
{
    const float* x        = (const float*)d_in[0];
    const float* rw       = (const float*)d_in[1];
    const float* rbias    = (const float*)d_in[2];
    const float* bn_gamma = (const float*)d_in[3];
    const float* bn_beta  = (const float*)d_in[4];
    const float* ln_gamma = (const float*)d_in[5];
    const float* ln_beta  = (const float*)d_in[6];
    float* out = (float*)d_out;

    k_spatial_reduce<<<(B_DIM * C_DIM) / 8, 256>>>(x);
    k_channel_stats <<<C_DIM / 8, 256>>>(bn_gamma, bn_beta, out);
    k_route         <<<B_DIM, 512>>>(rw, rbias, ln_gamma, ln_beta, out);
}

// round 6
// speedup vs baseline: 1.1011x; 1.1011x over previous
#include <cuda_runtime.h>

// Shapes (fixed):
//   x [64,512,32,32] fp32, HW=1024 contiguous
//   router_weights [512,16], router_bias [16]
//   bn_gamma/beta [512], ln_gamma/beta [512]
// Output fp32: new_x [64,512] | logits [64,16] | probs [64,16]

#define B_DIM 64
#define C_DIM 512
#define A_DIM 16
#define HW    1024
#define EPSF  1e-5f
#define NBLK  4096u          // total blocks (one warp per (b,c) tile, 8 warps/block)
#define NSURV 64u            // survivor blocks (one per batch row)

__device__ float    g_sum[B_DIM * C_DIM];   // [b*512 + c]
__device__ float    g_sq [B_DIM * C_DIM];
__device__ unsigned g_ctr = 0;              // monotonic across replays

__global__ __launch_bounds__(256) void k_fused(
    const float* __restrict__ x,
    const float* __restrict__ rw,        // [512,16]
    const float* __restrict__ rbias,     // [16]
    const float* __restrict__ bng,
    const float* __restrict__ bnb,
    const float* __restrict__ lng,
    const float* __restrict__ lnb,
    float* __restrict__ out)
{
    __shared__ float nx  [C_DIM];        // new_x row b
    __shared__ float nxl [C_DIM];        // nx[c] * ln_gamma[c]
    __shared__ float part_pa[256], part_sw[256], part_sq[256];
    __shared__ float redG[8], redH[8];
    __shared__ float lsh[A_DIM];
    __shared__ float sG, sHb;
    __shared__ unsigned sticket;

    const int tid  = threadIdx.x;
    const int lane = tid & 31;
    const int wid  = tid >> 5;

    // ---------------- Phase 1: per-(b,c) spatial sum + sumsq -----------------
    {
        unsigned warpId = blockIdx.x * 8u + (unsigned)wid;   // == b*512 + c
        const float4* p = reinterpret_cast<const float4*>(x) + (size_t)warpId * 256;
        float s = 0.f, q = 0.f;
#pragma unroll
        for (int k = 0; k < 8; ++k) {
            float4 v = __ldcs(p + k * 32 + lane);            // streaming: no reuse
            s += v.x + v.y + v.z + v.w;
            q += v.x * v.x + v.y * v.y + v.z * v.z + v.w * v.w;
        }
#pragma unroll
        for (int o = 16; o; o >>= 1) {
            s += __shfl_xor_sync(0xFFFFFFFFu, s, o);
            q += __shfl_xor_sync(0xFFFFFFFFu, q, o);
        }
        if (lane == 0) { g_sum[warpId] = s; g_sq[warpId] = q; }
    }

    // ---------------- Ticketed completion (monotonic, replay-safe) -----------
    __threadfence();
    __syncthreads();
    if (tid == 0) sticket = atomicAdd(&g_ctr, 1u);
    __syncthreads();
    const unsigned old = sticket;
    const unsigned idx = old & (NBLK - 1u);
    if (idx < NBLK - NSURV) return;                  // most blocks exit here
    const int b = (int)(idx - (NBLK - NSURV));       // survivor handles batch b

    if (tid == 0) {
        const unsigned target = (old - idx) + NBLK;  // launch-base + 4096
        while ((int)(*(volatile unsigned*)&g_ctr - target) < 0) __nanosleep(64);
    }
    __syncthreads();
    __threadfence();                                  // acquire all g_sum/g_sq

    // ---------------- Stage 2a: channel stats + new_x row b ------------------
    {
        const int c0 = tid, c1 = tid + 256;
        float s0 = 0.f, q0 = 0.f, s1 = 0.f, q1 = 0.f;
#pragma unroll 8
        for (int bb = 0; bb < B_DIM; ++bb) {
            s0 += g_sum[bb * C_DIM + c0];  q0 += g_sq[bb * C_DIM + c0];
            s1 += g_sum[bb * C_DIM + c1];  q1 += g_sq[bb * C_DIM + c1];
        }
        const float invM  = 1.0f / (float)(B_DIM * HW);
        const float invHW = 1.0f / (float)HW;

        float mu0 = s0 * invM, mu1 = s1 * invM;
        float r0 = rsqrtf(q0 * invM - mu0 * mu0 + EPSF);
        float r1 = rsqrtf(q1 * invM - mu1 * mu1 + EPSF);

        float n0 = bng[c0] * (g_sum[b * C_DIM + c0] * invHW - mu0) * r0 + bnb[c0];
        float n1 = bng[c1] * (g_sum[b * C_DIM + c1] * invHW - mu1) * r1 + bnb[c1];
        nx[c0] = n0;  nx[c1] = n1;
        out[b * C_DIM + c0] = n0;
        out[b * C_DIM + c1] = n1;

        float lg0 = lng[c0], lg1 = lng[c1];
        nxl[c0] = n0 * lg0;  nxl[c1] = n1 * lg1;

        // block-reduce G = sum nx*ln_gamma, Hb = sum nx*ln_beta
        float gp = n0 * lg0 + n1 * lg1;
        float hp = n0 * lnb[c0] + n1 * lnb[c1];
#pragma unroll
        for (int o = 16; o; o >>= 1) {
            gp += __shfl_xor_sync(0xFFFFFFFFu, gp, o);
            hp += __shfl_xor_sync(0xFFFFFFFFu, hp, o);
        }
        if (lane == 0) { redG[wid] = gp; redH[wid] = hp; }
    }
    __syncthreads();
    if (tid == 0) {
        float g = 0.f, h = 0.f;
#pragma unroll
        for (int i = 0; i < 8; ++i) { g += redG[i]; h += redH[i]; }
        sG = g; sHb = h;
    }

    // ---------------- Stage 2b: fused LN-weight + dot partials ---------------
    // thread (a = tid&15, grp = tid>>4) covers c in [grp*32, grp*32+32)
    // Coalesced: for fixed c, a=0..15 are consecutive floats of rw.
    {
        const int a   = tid & 15;
        const int grp = tid >> 4;
        const float* wp  = rw  + (grp * 32) * A_DIM + a;
        const float* nlp = nxl + grp * 32;
        float pa = 0.f, sw = 0.f, sq = 0.f;
#pragma unroll
        for (int j = 0; j < 32; ++j) {
            float wv = wp[j * A_DIM];
            pa += nlp[j] * wv;
            sw += wv;
            sq += wv * wv;
        }
        part_pa[tid] = pa;  part_sw[tid] = sw;  part_sq[tid] = sq;
    }
    __syncthreads();

    // ---------------- Stage 2c: logits + softmax ----------------------------
    float* logits_out = out + B_DIM * C_DIM;
    float* probs_out  = logits_out + B_DIM * A_DIM;

    if (tid < A_DIM) {
        float P = 0.f, SW = 0.f, SQ = 0.f;
#pragma unroll
        for (int g = 0; g < 16; ++g) {
            P  += part_pa[g * 16 + tid];
            SW += part_sw[g * 16 + tid];
            SQ += part_sq[g * 16 + tid];
        }
        const float invC = 1.0f / (float)C_DIM;
        float m    = SW * invC;
        float rstd = rsqrtf(SQ * invC - m * m + EPSF);
        float logit = rstd * (P - m * sG) + sHb + rbias[tid];
        lsh[tid] = logit;
        logits_out[b * A_DIM + tid] = logit;
    }
    __syncthreads();

    if (tid == 0) {
        float mx = lsh[0];
#pragma unroll
        for (int a = 1; a < A_DIM; ++a) mx = fmaxf(mx, lsh[a]);
        float e[A_DIM]; float ssum = 0.f;
#pragma unroll
        for (int a = 0; a < A_DIM; ++a) { e[a] = __expf(lsh[a] - mx); ssum += e[a]; }
        float inv = 1.0f / ssum;
#pragma unroll
        for (int a = 0; a < A_DIM; ++a) probs_out[b * A_DIM + a] = e[a] * inv;
    }
}

extern "C" void kernel_launch(void* const* d_in, const int* in_sizes, int n_in,
                              void* d_out, int out_size)
{
    const float* x        = (const float*)d_in[0];
    const float* rw       = (const float*)d_in[1];
    const float* rbias    = (const float*)d_in[2];
    const float* bn_gamma = (const float*)d_in[3];
    const float* bn_beta  = (const float*)d_in[4];
    const float* ln_gamma = (const float*)d_in[5];
    const float* ln_beta  = (const float*)d_in[6];

    k_fused<<<NBLK, 256>>>(x, rw, rbias, bn_gamma, bn_beta,
                           ln_gamma, ln_beta, (float*)d_out);
}

// round 7
// speedup vs baseline: 1.1676x; 1.0604x over previous
#include <cuda_runtime.h>

// Shapes (fixed):
//   x [64,512,32,32] fp32 (HW=1024 contiguous)
//   router_weights [512,16], router_bias [16]
//   bn_gamma/beta [512], ln_gamma/beta [512]
// Output fp32: new_x [64,512] | logits [64,16] | probs [64,16]

#define B_DIM 64
#define C_DIM 512
#define A_DIM 16
#define HW    1024
#define EPSF  1e-5f
#define NBLK   4096u   // phase-1 blocks
#define NSURV  64u     // survivor blocks (one per batch row)
#define PERIOD 4160u   // counter increments per launch = NBLK + NSURV

__device__ float    g_sum[B_DIM * C_DIM];   // [b*512 + c]
__device__ float    g_sq [B_DIM * C_DIM];
__device__ float2   g_stats[C_DIM];         // (mu, rstd) per channel
__device__ unsigned g_ctr = 0;              // monotonic across replays

__global__ __launch_bounds__(256) void k_fused(
    const float* __restrict__ x,
    const float* __restrict__ rw,        // [512,16]
    const float* __restrict__ rbias,     // [16]
    const float* __restrict__ bng,
    const float* __restrict__ bnb,
    const float* __restrict__ lng,
    const float* __restrict__ lnb,
    float* __restrict__ out)
{
    __shared__ float nxl [C_DIM];        // new_x[b,c] * ln_gamma[c]
    __shared__ float part_pa[256], part_sw[256], part_sq[256];
    __shared__ float redG[8], redH[8];
    __shared__ float lsh[A_DIM];
    __shared__ float sG, sHb;
    __shared__ unsigned sticket;

    const int tid  = threadIdx.x;
    const int lane = tid & 31;
    const int wid  = tid >> 5;

    // ---------------- Phase 1: per-(b,c) spatial sum + sumsq -----------------
    {
        unsigned warpId = blockIdx.x * 8u + (unsigned)wid;   // == b*512 + c
        const float4* p = reinterpret_cast<const float4*>(x) + (size_t)warpId * 256;
        float s = 0.f, q = 0.f;
#pragma unroll
        for (int k = 0; k < 8; ++k) {
            float4 v = p[k * 32 + lane];
            s += v.x + v.y + v.z + v.w;
            q += v.x * v.x + v.y * v.y + v.z * v.z + v.w * v.w;
        }
#pragma unroll
        for (int o = 16; o; o >>= 1) {
            s += __shfl_xor_sync(0xFFFFFFFFu, s, o);
            q += __shfl_xor_sync(0xFFFFFFFFu, q, o);
        }
        if (lane == 0) { g_sum[warpId] = s; g_sq[warpId] = q; }
    }

    // ---------------- Ticket 1: wait for all phase-1 writes ------------------
    __threadfence();
    __syncthreads();
    if (tid == 0) sticket = atomicAdd(&g_ctr, 1u);
    __syncthreads();
    const unsigned old  = sticket;
    const unsigned idx  = old % PERIOD;                 // 0 .. 4095 for phase-1 tickets
    const unsigned base = old - idx;                    // multiple of PERIOD
    if (idx < NBLK - NSURV) return;                     // 4032 blocks exit
    const int slice = (int)(idx - (NBLK - NSURV));      // 0 .. 63

    if (tid == 0) {
        const unsigned t1 = base + NBLK;
        while ((int)(*(volatile unsigned*)&g_ctr - t1) < 0) __nanosleep(32);
    }
    __syncthreads();
    __threadfence();

    // ---------------- Round 1: batch stats for 8 channels --------------------
    // warp w handles channel c = slice*8 + w; lane reduces over b (2 each).
    {
        const int c = slice * 8 + wid;
        float S = g_sum[lane * C_DIM + c] + g_sum[(lane + 32) * C_DIM + c];
        float Q = g_sq [lane * C_DIM + c] + g_sq [(lane + 32) * C_DIM + c];
#pragma unroll
        for (int o = 16; o; o >>= 1) {
            S += __shfl_xor_sync(0xFFFFFFFFu, S, o);
            Q += __shfl_xor_sync(0xFFFFFFFFu, Q, o);
        }
        if (lane == 0) {
            const float invM = 1.0f / (float)(B_DIM * HW);
            float mu = S * invM;
            float rstd = rsqrtf(Q * invM - mu * mu + EPSF);
            g_stats[c] = make_float2(mu, rstd);
        }
    }

    // ---------------- Ticket 2: wait for all 64 stats slices -----------------
    __threadfence();
    __syncthreads();
    if (tid == 0) {
        atomicAdd(&g_ctr, 1u);
        const unsigned t2 = base + PERIOD;
        while ((int)(*(volatile unsigned*)&g_ctr - t2) < 0) __nanosleep(32);
    }
    __syncthreads();
    __threadfence();

    // ---------------- Round 2: new_x row b + routing -------------------------
    const int b = slice;
    {
        const int c0 = tid, c1 = tid + 256;
        float2 st0 = g_stats[c0], st1 = g_stats[c1];
        const float invHW = 1.0f / (float)HW;

        float n0 = bng[c0] * (g_sum[b * C_DIM + c0] * invHW - st0.x) * st0.y + bnb[c0];
        float n1 = bng[c1] * (g_sum[b * C_DIM + c1] * invHW - st1.x) * st1.y + bnb[c1];
        out[b * C_DIM + c0] = n0;
        out[b * C_DIM + c1] = n1;

        float lg0 = lng[c0], lg1 = lng[c1];
        nxl[c0] = n0 * lg0;  nxl[c1] = n1 * lg1;

        // block-reduce G = sum nx*ln_gamma, H = sum nx*ln_beta
        float gp = n0 * lg0 + n1 * lg1;
        float hp = n0 * lnb[c0] + n1 * lnb[c1];
#pragma unroll
        for (int o = 16; o; o >>= 1) {
            gp += __shfl_xor_sync(0xFFFFFFFFu, gp, o);
            hp += __shfl_xor_sync(0xFFFFFFFFu, hp, o);
        }
        if (lane == 0) { redG[wid] = gp; redH[wid] = hp; }
    }
    __syncthreads();
    if (tid == 0) {
        float g = 0.f, h = 0.f;
#pragma unroll
        for (int i = 0; i < 8; ++i) { g += redG[i]; h += redH[i]; }
        sG = g; sHb = h;
    }

    // Fused LN-weight + dot partials: thread (a = tid&15, grp = tid>>4)
    {
        const int a   = tid & 15;
        const int grp = tid >> 4;
        const float* wp  = rw  + (grp * 32) * A_DIM + a;
        const float* nlp = nxl + grp * 32;
        float pa = 0.f, sw = 0.f, sq = 0.f;
#pragma unroll
        for (int j = 0; j < 32; ++j) {
            float wv = wp[j * A_DIM];
            pa += nlp[j] * wv;
            sw += wv;
            sq += wv * wv;
        }
        part_pa[tid] = pa;  part_sw[tid] = sw;  part_sq[tid] = sq;
    }
    __syncthreads();

    // Logits + softmax
    float* logits_out = out + B_DIM * C_DIM;
    float* probs_out  = logits_out + B_DIM * A_DIM;

    if (tid < A_DIM) {
        float P = 0.f, SW = 0.f, SQ = 0.f;
#pragma unroll
        for (int g = 0; g < 16; ++g) {
            P  += part_pa[g * 16 + tid];
            SW += part_sw[g * 16 + tid];
            SQ += part_sq[g * 16 + tid];
        }
        const float invC = 1.0f / (float)C_DIM;
        float m    = SW * invC;
        float rstd = rsqrtf(SQ * invC - m * m + EPSF);
        float logit = rstd * (P - m * sG) + sHb + rbias[tid];
        lsh[tid] = logit;
        logits_out[b * A_DIM + tid] = logit;
    }
    __syncthreads();

    if (tid == 0) {
        float mx = lsh[0];
#pragma unroll
        for (int a = 1; a < A_DIM; ++a) mx = fmaxf(mx, lsh[a]);
        float e[A_DIM]; float ssum = 0.f;
#pragma unroll
        for (int a = 0; a < A_DIM; ++a) { e[a] = __expf(lsh[a] - mx); ssum += e[a]; }
        float inv = 1.0f / ssum;
#pragma unroll
        for (int a = 0; a < A_DIM; ++a) probs_out[b * A_DIM + a] = e[a] * inv;
    }
}

extern "C" void kernel_launch(void* const* d_in, const int* in_sizes, int n_in,
                              void* d_out, int out_size)
{
    const float* x        = (const float*)d_in[0];
    const float* rw       = (const float*)d_in[1];
    const float* rbias    = (const float*)d_in[2];
    const float* bn_gamma = (const float*)d_in[3];
    const float* bn_beta  = (const float*)d_in[4];
    const float* ln_gamma = (const float*)d_in[5];
    const float* ln_beta  = (const float*)d_in[6];

    k_fused<<<NBLK, 256>>>(x, rw, rbias, bn_gamma, bn_beta,
                           ln_gamma, ln_beta, (float*)d_out);
}

// round 8
// speedup vs baseline: 1.2045x; 1.0316x over previous
#include <cuda_runtime.h>

// Shapes (fixed):
//   x [64,512,32,32] fp32 (HW=1024 contiguous)
//   router_weights [512,16], router_bias [16]
//   bn_gamma/beta [512], ln_gamma/beta [512]
// Output fp32: new_x [64,512] | logits [64,16] | probs [64,16]

#define B_DIM 64
#define C_DIM 512
#define A_DIM 16
#define HW    1024
#define EPSF  1e-5f
#define NBLK   1024u   // single wave: 1024 <= 148 SMs * 8 blocks
#define TPB    4u      // warp-tiles per warp (1024*8*4 = 32768 = B*C)
#define NSURV  64u     // survivor blocks (one per batch row)
#define PERIOD 1088u   // counter increments per launch = NBLK + NSURV

__device__ float    g_sum[B_DIM * C_DIM];   // [b*512 + c]
__device__ float    g_sq [B_DIM * C_DIM];
__device__ float2   g_stats[C_DIM];         // (mu, rstd) per channel
__device__ unsigned g_ctr = 0;              // monotonic across replays

__global__ __launch_bounds__(256, 8) void k_fused(
    const float* __restrict__ x,
    const float* __restrict__ rw,        // [512,16]
    const float* __restrict__ rbias,     // [16]
    const float* __restrict__ bng,
    const float* __restrict__ bnb,
    const float* __restrict__ lng,
    const float* __restrict__ lnb,
    float* __restrict__ out)
{
    __shared__ float nxl [C_DIM];        // new_x[b,c] * ln_gamma[c]
    __shared__ float part_pa[256], part_sw[256], part_sq[256];
    __shared__ float redG[8], redH[8];
    __shared__ float lsh[A_DIM];
    __shared__ float sG, sHb;
    __shared__ unsigned sticket;

    const int tid  = threadIdx.x;
    const int lane = tid & 31;
    const int wid  = tid >> 5;

    // ---------------- Phase 1: per-(b,c) spatial sum + sumsq -----------------
    // Each warp reduces TPB=4 consecutive 1024-float tiles (one (b,c) each).
    {
        unsigned tile0 = (blockIdx.x * TPB) * 8u + (unsigned)wid;
#pragma unroll 1
        for (unsigned i = 0; i < TPB; ++i) {
            unsigned warpId = tile0 + i * 8u;                 // == b*512 + c
            const float4* p = reinterpret_cast<const float4*>(x)
                            + (size_t)warpId * 256;
            float s = 0.f, q = 0.f;
#pragma unroll
            for (int k = 0; k < 8; ++k) {
                float4 v = p[k * 32 + lane];
                s += v.x + v.y + v.z + v.w;
                q += v.x * v.x + v.y * v.y + v.z * v.z + v.w * v.w;
            }
#pragma unroll
            for (int o = 16; o; o >>= 1) {
                s += __shfl_xor_sync(0xFFFFFFFFu, s, o);
                q += __shfl_xor_sync(0xFFFFFFFFu, q, o);
            }
            if (lane == 0) { g_sum[warpId] = s; g_sq[warpId] = q; }
        }
    }

    // ---------------- Ticket 1: wait for all phase-1 writes ------------------
    __threadfence();
    __syncthreads();
    if (tid == 0) sticket = atomicAdd(&g_ctr, 1u);
    __syncthreads();
    const unsigned old  = sticket;
    const unsigned idx  = old % PERIOD;                 // 0..1023 for phase-1 tickets
    const unsigned base = old - idx;                    // multiple of PERIOD
    if (idx < NBLK - NSURV) return;                     // 960 blocks exit
    const int slice = (int)(idx - (NBLK - NSURV));      // 0 .. 63

    if (tid == 0) {
        const unsigned t1 = base + NBLK;
        while ((int)(*(volatile unsigned*)&g_ctr - t1) < 0) __nanosleep(32);
    }
    __syncthreads();
    __threadfence();

    // ---------------- Round 1: batch stats for 8 channels --------------------
    // warp w handles channel c = slice*8 + w; lanes reduce over b (2 each).
    {
        const int c = slice * 8 + wid;
        float S = g_sum[lane * C_DIM + c] + g_sum[(lane + 32) * C_DIM + c];
        float Q = g_sq [lane * C_DIM + c] + g_sq [(lane + 32) * C_DIM + c];
#pragma unroll
        for (int o = 16; o; o >>= 1) {
            S += __shfl_xor_sync(0xFFFFFFFFu, S, o);
            Q += __shfl_xor_sync(0xFFFFFFFFu, Q, o);
        }
        if (lane == 0) {
            const float invM = 1.0f / (float)(B_DIM * HW);
            float mu = S * invM;
            float rstd = rsqrtf(Q * invM - mu * mu + EPSF);
            g_stats[c] = make_float2(mu, rstd);
        }
    }

    // ---------------- Ticket 2: wait for all 64 stats slices -----------------
    __threadfence();
    __syncthreads();
    if (tid == 0) {
        atomicAdd(&g_ctr, 1u);
        const unsigned t2 = base + PERIOD;
        while ((int)(*(volatile unsigned*)&g_ctr - t2) < 0) __nanosleep(32);
    }
    __syncthreads();
    __threadfence();

    // ---------------- Round 2: new_x row b + routing -------------------------
    const int b = slice;
    {
        const int c0 = tid, c1 = tid + 256;
        float2 st0 = g_stats[c0], st1 = g_stats[c1];
        const float invHW = 1.0f / (float)HW;

        float n0 = bng[c0] * (g_sum[b * C_DIM + c0] * invHW - st0.x) * st0.y + bnb[c0];
        float n1 = bng[c1] * (g_sum[b * C_DIM + c1] * invHW - st1.x) * st1.y + bnb[c1];
        out[b * C_DIM + c0] = n0;
        out[b * C_DIM + c1] = n1;

        float lg0 = lng[c0], lg1 = lng[c1];
        nxl[c0] = n0 * lg0;  nxl[c1] = n1 * lg1;

        // block-reduce G = sum nx*ln_gamma, H = sum nx*ln_beta
        float gp = n0 * lg0 + n1 * lg1;
        float hp = n0 * lnb[c0] + n1 * lnb[c1];
#pragma unroll
        for (int o = 16; o; o >>= 1) {
            gp += __shfl_xor_sync(0xFFFFFFFFu, gp, o);
            hp += __shfl_xor_sync(0xFFFFFFFFu, hp, o);
        }
        if (lane == 0) { redG[wid] = gp; redH[wid] = hp; }
    }
    __syncthreads();
    if (tid == 0) {
        float g = 0.f, h = 0.f;
#pragma unroll
        for (int i = 0; i < 8; ++i) { g += redG[i]; h += redH[i]; }
        sG = g; sHb = h;
    }

    // Fused LN-weight + dot partials: thread (a = tid&15, grp = tid>>4)
    {
        const int a   = tid & 15;
        const int grp = tid >> 4;
        const float* wp  = rw  + (grp * 32) * A_DIM + a;
        const float* nlp = nxl + grp * 32;
        float pa = 0.f, sw = 0.f, sq = 0.f;
#pragma unroll
        for (int j = 0; j < 32; ++j) {
            float wv = wp[j * A_DIM];
            pa += nlp[j] * wv;
            sw += wv;
            sq += wv * wv;
        }
        part_pa[tid] = pa;  part_sw[tid] = sw;  part_sq[tid] = sq;
    }
    __syncthreads();

    // Logits + softmax
    float* logits_out = out + B_DIM * C_DIM;
    float* probs_out  = logits_out + B_DIM * A_DIM;

    if (tid < A_DIM) {
        float P = 0.f, SW = 0.f, SQ = 0.f;
#pragma unroll
        for (int g = 0; g < 16; ++g) {
            P  += part_pa[g * 16 + tid];
            SW += part_sw[g * 16 + tid];
            SQ += part_sq[g * 16 + tid];
        }
        const float invC = 1.0f / (float)C_DIM;
        float m    = SW * invC;
        float rstd = rsqrtf(SQ * invC - m * m + EPSF);
        float logit = rstd * (P - m * sG) + sHb + rbias[tid];
        lsh[tid] = logit;
        logits_out[b * A_DIM + tid] = logit;
    }
    __syncthreads();

    if (tid == 0) {
        float mx = lsh[0];
#pragma unroll
        for (int a = 1; a < A_DIM; ++a) mx = fmaxf(mx, lsh[a]);
        float e[A_DIM]; float ssum = 0.f;
#pragma unroll
        for (int a = 0; a < A_DIM; ++a) { e[a] = __expf(lsh[a] - mx); ssum += e[a]; }
        float inv = 1.0f / ssum;
#pragma unroll
        for (int a = 0; a < A_DIM; ++a) probs_out[b * A_DIM + a] = e[a] * inv;
    }
}

extern "C" void kernel_launch(void* const* d_in, const int* in_sizes, int n_in,
                              void* d_out, int out_size)
{
    const float* x        = (const float*)d_in[0];
    const float* rw       = (const float*)d_in[1];
    const float* rbias    = (const float*)d_in[2];
    const float* bn_gamma = (const float*)d_in[3];
    const float* bn_beta  = (const float*)d_in[4];
    const float* ln_gamma = (const float*)d_in[5];
    const float* ln_beta  = (const float*)d_in[6];

    k_fused<<<NBLK, 256>>>(x, rw, rbias, bn_gamma, bn_beta,
                           ln_gamma, ln_beta, (float*)d_out);
}